// round 8
// baseline (speedup 1.0000x reference)
#include <cuda_runtime.h>
#include <math.h>
#include <stdint.h>

// ---------------------------------------------------------------------------
// YoloLoss: predictions (N,7,7,90) f32, target (N,7,7,85) f32 -> 4 scalars
// 4-stage cp.async.bulk smem pipeline, 32-cell tiles (22400 B), 2 blocks/SM.
//   - producer (tid 0) runs up to 4 tiles ahead via mbarrier expect_tx
//   - consumers: 8 threads/cell class loss (pred via float2 LDS), 1 thread/cell
//     box/IoU math; per-warp empty arrives (count=8)
//   - last-block-done fused finalize (self-resets for graph replay)
// ---------------------------------------------------------------------------

#define PRED_C 90
#define TGT_C  85

static constexpr int THREADS   = 256;
static constexpr int WARPS     = THREADS / 32;
static constexpr int NBLOCKS   = 304;               // 2 per SM (152 SMs)
static constexpr int STAGES    = 4;
static constexpr int TILE      = 32;                // cells per tile
static constexpr int SP_FLOATS = TILE * PRED_C;     // 2880
static constexpr int ST_FLOATS = TILE * TGT_C;      // 2720
static constexpr int SP_BYTES  = SP_FLOATS * 4;     // 11520
static constexpr int ST_BYTES  = ST_FLOATS * 4;     // 10880
static constexpr int TILE_BYTES = SP_BYTES + ST_BYTES;       // 22400
static constexpr int DYN_SMEM  = STAGES * TILE_BYTES + 128;  // + barriers

__device__ float    g_partials[NBLOCKS * 4];
__device__ unsigned g_count = 0;

// ---- PTX helpers ----
__device__ __forceinline__ uint32_t smem_u32(const void* p) {
    return (uint32_t)__cvta_generic_to_shared(p);
}
#define MBAR_INIT(addr, cnt) \
    asm volatile("mbarrier.init.shared.b64 [%0], %1;" :: "r"(addr), "r"(cnt) : "memory")
#define MBAR_EXPECT_TX(addr, bytes) \
    asm volatile("mbarrier.arrive.expect_tx.shared.b64 _, [%0], %1;" :: "r"(addr), "r"(bytes) : "memory")
#define MBAR_ARRIVE(addr) \
    asm volatile("mbarrier.arrive.shared.b64 _, [%0];" :: "r"(addr) : "memory")
#define MBAR_WAIT_PARITY(addr, ph) do {                                        \
    asm volatile("{\n\t.reg .pred P1;\n"                                       \
                 "WL_%=:\n\t"                                                  \
                 "mbarrier.try_wait.parity.acquire.cta.shared::cta.b64 P1, [%0], %1;\n\t" \
                 "@!P1 bra WL_%=;\n\t}"                                        \
                 :: "r"(addr), "r"(ph) : "memory");                            \
} while (0)
#define BULK_G2S(dst_smem, src_gmem, bytes, mbar) \
    asm volatile("cp.async.bulk.shared::cluster.global.mbarrier::complete_tx::bytes " \
                 "[%0], [%1], %2, [%3];"                                       \
                 :: "r"(dst_smem), "l"(src_gmem), "r"(bytes), "r"(mbar) : "memory")

__device__ __forceinline__ float iou_cxcywh(float ax, float ay, float aw, float ah,
                                            float bx, float by, float bw, float bh) {
    float ax1 = ax - aw * 0.5f, ay1 = ay - ah * 0.5f;
    float ax2 = ax + aw * 0.5f, ay2 = ay + ah * 0.5f;
    float bx1 = bx - bw * 0.5f, by1 = by - bh * 0.5f;
    float bx2 = bx + bw * 0.5f, by2 = by + bh * 0.5f;
    float iw = fmaxf(fminf(ax2, bx2) - fmaxf(ax1, bx1), 0.0f);
    float ih = fmaxf(fminf(ay2, by2) - fmaxf(ay1, by1), 0.0f);
    float inter  = iw * ih;
    float area_a = (ax2 - ax1) * (ay2 - ay1);
    float area_b = (bx2 - bx1) * (by2 - by1);
    return inter / (area_a + area_b - inter);
}

__device__ __forceinline__ float sgnsqrt(float x) {
    float s = (x > 0.0f) ? 1.0f : ((x < 0.0f) ? -1.0f : 0.0f);
    return s * sqrtf(fabsf(x) + 1e-6f);
}

// Full per-cell box/obj/noobj math (reference semantics).
__device__ __forceinline__ void cell_box_math(
    const float* __restrict__ pb,   // preds[80..89]
    const float* __restrict__ tb,   // target[80..84]
    float& aC, float& aO, float& aN) {
    float p80 = pb[0];
    float b2x = pb[1], b2y = pb[2], b2w = pb[3], b2h = pb[4];
    float p85 = pb[5];
    float b1x = pb[6], b1y = pb[7], b1w = pb[8], b1h = pb[9];
    float obj = tb[0];
    float tbx = tb[1], tby = tb[2], tbw = tb[3], tbh = tb[4];

    float iou1 = iou_cxcywh(b1x, b1y, b1w, b1h, tbx, tby, tbw, tbh);
    float iou2 = iou_cxcywh(b2x, b2y, b2w, b2h, tbx, tby, tbw, tbh);
    bool pick2 = iou2 > iou1;   // numpy argmax: first max wins ties

    float bx = pick2 ? b2x : b1x;
    float bw = pick2 ? b2w : b1w;
    float bh = pick2 ? b2h : b1h;
    float op = pick2 ? p80 : p85;

    // pred_boxes = obj * chosen box; center loss uses cx only ([..., :-3])
    float dc = fmaf(obj, bx, -tbx);
    aC = fmaf(dc, dc, aC);
    float dw = sgnsqrt(obj * bw) - sqrtf(tbw);
    aC = fmaf(dw, dw, aC);
    float dh = sgnsqrt(obj * bh) - sqrtf(tbh);
    aC = fmaf(dh, dh, aC);

    float e1 = fmaf(obj, op, -obj);
    aO = fmaf(e1, e1, aO);
    float e2 = fmaf(1.0f - obj, op, -obj);
    aN = fmaf(e2, e2, aN);
}

__global__ __launch_bounds__(THREADS)
void yolo_loss_tma(const float* __restrict__ P, const float* __restrict__ T,
                   float* __restrict__ out, int ncells) {
    extern __shared__ __align__(16) unsigned char dyn[];
    float* spb[STAGES];  float* stb[STAGES];
    #pragma unroll
    for (int s = 0; s < STAGES; s++) {
        spb[s] = (float*)(dyn + s * TILE_BYTES);
        stb[s] = spb[s] + SP_FLOATS;
    }
    uint64_t* bars = (uint64_t*)(dyn + STAGES * TILE_BYTES);  // [0..3]=full,[4..7]=empty
    uint32_t full_a[STAGES], empty_a[STAGES];
    #pragma unroll
    for (int s = 0; s < STAGES; s++) {
        full_a[s]  = smem_u32(&bars[s]);
        empty_a[s] = smem_u32(&bars[STAGES + s]);
    }

    __shared__ float  red[4][WARPS];
    __shared__ double dred[4][WARPS];
    __shared__ int    s_last;

    const unsigned FULL = 0xffffffffu;
    const int tid  = threadIdx.x;
    const int lane = tid & 31;
    const int wrp  = tid >> 5;

    const int ntiles = ncells / TILE;
    const int rem    = ncells - ntiles * TILE;
    const int nmine = ((int)blockIdx.x < ntiles)
                    ? (ntiles - 1 - (int)blockIdx.x) / (int)gridDim.x + 1 : 0;

    if (tid == 0) {
        #pragma unroll
        for (int s = 0; s < STAGES; s++) {
            MBAR_INIT(full_a[s], 1);
            MBAR_INIT(empty_a[s], WARPS);
        }
    }
    __syncthreads();

    // ---- Prologue: issue up to STAGES tiles ----
    if (tid == 0) {
        int pre = nmine < STAGES ? nmine : STAGES;
        for (int i = 0; i < pre; i++) {
            int tl = blockIdx.x + i * gridDim.x;
            MBAR_EXPECT_TX(full_a[i], TILE_BYTES);
            BULK_G2S(smem_u32(spb[i]), P + (size_t)tl * SP_FLOATS, SP_BYTES, full_a[i]);
            BULK_G2S(smem_u32(stb[i]), T + (size_t)tl * ST_FLOATS, ST_BYTES, full_a[i]);
        }
    }

    float aC = 0.0f, aO = 0.0f, aN = 0.0f, aL = 0.0f;
    const int cc = tid >> 3;          // cell for class loss (8 threads/cell)
    const int k0 = (tid & 7) * 10;    // class sub-range start

    for (int it = 0; it < nmine; it++) {
        const int b  = it & (STAGES - 1);
        const int ph = (it / STAGES) & 1;
        MBAR_WAIT_PARITY(full_a[b], ph);

        const float* sp = spb[b];
        const float* st = stb[b];

        // ---- class loss: 8 threads/cell, 10 classes; pred via float2 ----
        {
            // pred byte offset = cc*360 + k0*4 = cc*360 + (tid&7)*40 -> 8B aligned
            const float2* pc2 = (const float2*)(sp + cc * PRED_C + k0);
            const float*  tc  = st + cc * TGT_C;
            float obj = tc[80];
            const float* tk = tc + k0;
            float l0 = 0.0f, l1 = 0.0f;
            #pragma unroll
            for (int j = 0; j < 5; j++) {
                float2 pv = pc2[j];
                float d0 = fmaf(pv.x, obj, -tk[2 * j]);     l0 = fmaf(d0, d0, l0);
                float d1 = fmaf(pv.y, obj, -tk[2 * j + 1]); l1 = fmaf(d1, d1, l1);
            }
            aL += l0 + l1;
        }

        // ---- box math: one thread per cell (warp 0) ----
        if (tid < TILE) {
            cell_box_math(sp + tid * PRED_C + 80, st + tid * TGT_C + 80, aC, aO, aN);
        }

        // ---- per-warp empty arrive ----
        __syncwarp();
        if (lane == 0) MBAR_ARRIVE(empty_a[b]);

        // ---- producer: refill this stage for tile it+STAGES ----
        if (tid == 0) {
            int ti = it + STAGES;
            if (ti < nmine) {
                MBAR_WAIT_PARITY(empty_a[b], ph);
                int tl = blockIdx.x + ti * gridDim.x;
                MBAR_EXPECT_TX(full_a[b], TILE_BYTES);
                BULK_G2S(smem_u32(spb[b]), P + (size_t)tl * SP_FLOATS, SP_BYTES, full_a[b]);
                BULK_G2S(smem_u32(stb[b]), T + (size_t)tl * ST_FLOATS, ST_BYTES, full_a[b]);
            }
        }
    }

    // ---- remainder cells (not taken for 401408): block 0, direct global ----
    if (rem > 0 && blockIdx.x == 0 && tid < rem) {
        int cell = ntiles * TILE + tid;
        const float* p = P + (size_t)cell * PRED_C;
        const float* t = T + (size_t)cell * TGT_C;
        float obj = t[80];
        for (int k = 0; k < 80; k++) {
            float d = fmaf(p[k], obj, -t[k]);
            aL = fmaf(d, d, aL);
        }
        float pb[10], tb[5];
        #pragma unroll
        for (int k = 0; k < 10; k++) pb[k] = p[80 + k];
        #pragma unroll
        for (int k = 0; k < 5; k++)  tb[k] = t[80 + k];
        cell_box_math(pb, tb, aC, aO, aN);
    }

    // ---- Block reduction ----
    #pragma unroll
    for (int off = 16; off > 0; off >>= 1) {
        aC += __shfl_xor_sync(FULL, aC, off);
        aO += __shfl_xor_sync(FULL, aO, off);
        aN += __shfl_xor_sync(FULL, aN, off);
        aL += __shfl_xor_sync(FULL, aL, off);
    }
    if (lane == 0) {
        red[0][wrp] = aC; red[1][wrp] = aO; red[2][wrp] = aN; red[3][wrp] = aL;
    }
    __syncthreads();
    if (tid == 0) {
        float s0 = 0, s1 = 0, s2 = 0, s3 = 0;
        #pragma unroll
        for (int w = 0; w < WARPS; w++) {
            s0 += red[0][w]; s1 += red[1][w]; s2 += red[2][w]; s3 += red[3][w];
        }
        g_partials[blockIdx.x * 4 + 0] = s0;
        g_partials[blockIdx.x * 4 + 1] = s1;
        g_partials[blockIdx.x * 4 + 2] = s2;
        g_partials[blockIdx.x * 4 + 3] = s3;
        __threadfence();
        unsigned prev = atomicAdd(&g_count, 1u);
        s_last = (prev == gridDim.x - 1) ? 1 : 0;
    }
    __syncthreads();

    // ---- Last block finalizes & resets counter for graph replay ----
    if (s_last) {
        double v0 = 0, v1 = 0, v2 = 0, v3 = 0;
        for (int b = tid; b < (int)gridDim.x; b += THREADS) {
            v0 += (double)__ldcg(&g_partials[b * 4 + 0]);
            v1 += (double)__ldcg(&g_partials[b * 4 + 1]);
            v2 += (double)__ldcg(&g_partials[b * 4 + 2]);
            v3 += (double)__ldcg(&g_partials[b * 4 + 3]);
        }
        #pragma unroll
        for (int off = 16; off > 0; off >>= 1) {
            v0 += __shfl_xor_sync(FULL, v0, off);
            v1 += __shfl_xor_sync(FULL, v1, off);
            v2 += __shfl_xor_sync(FULL, v2, off);
            v3 += __shfl_xor_sync(FULL, v3, off);
        }
        if (lane == 0) {
            dred[0][wrp] = v0; dred[1][wrp] = v1; dred[2][wrp] = v2; dred[3][wrp] = v3;
        }
        __syncthreads();
        if (tid == 0) {
            double c = 0, o = 0, n = 0, cl = 0;
            #pragma unroll
            for (int w = 0; w < WARPS; w++) {
                c += dred[0][w]; o += dred[1][w]; n += dred[2][w]; cl += dred[3][w];
            }
            out[0] = (float)(c * 5.0);   // coords (LAMBDA_COORDS)
            out[1] = (float)o;           // obj
            out[2] = (float)(n * 0.5);   // noobj (LAMBDA_NOOBJ)
            out[3] = (float)cl;          // classes
            atomicExch(&g_count, 0u);    // reset for next graph replay
        }
    }
}

extern "C" void kernel_launch(void* const* d_in, const int* in_sizes, int n_in,
                              void* d_out, int out_size) {
    const float* P = (const float*)d_in[0];   // predictions
    const float* T = (const float*)d_in[1];   // target
    float* out = (float*)d_out;

    int ncells = in_sizes[0] / PRED_C;        // 8192*7*7 = 401408

    cudaFuncSetAttribute(yolo_loss_tma,
                         cudaFuncAttributeMaxDynamicSharedMemorySize, DYN_SMEM);
    yolo_loss_tma<<<NBLOCKS, THREADS, DYN_SMEM>>>(P, T, out, ncells);
}

// round 9
// speedup vs baseline: 1.0036x; 1.0036x over previous
#include <cuda_runtime.h>
#include <math.h>
#include <stdint.h>

// ---------------------------------------------------------------------------
// YoloLoss: predictions (N,7,7,90) f32, target (N,7,7,85) f32 -> 4 scalars
// 4-stage x 64-cell cp.async.bulk pipeline, 1 block/SM (512 thr, 179KB smem).
//   - producer (tid 0) runs up to 4 tiles ahead via mbarrier expect_tx
//   - class loss: 8 threads/cell, pred via float2 LDS
//   - box/IoU math: warps 14-15 (tid >= 448), decoupled from producer warp
//   - per-warp empty arrives (count = 16)
//   - last-block-done fused finalize (self-resets for graph replay)
// ---------------------------------------------------------------------------

#define PRED_C 90
#define TGT_C  85

static constexpr int THREADS   = 512;
static constexpr int WARPS     = THREADS / 32;      // 16
static constexpr int NBLOCKS   = 152;               // 1 per SM
static constexpr int STAGES    = 4;
static constexpr int TILE      = 64;                // cells per tile
static constexpr int SP_FLOATS = TILE * PRED_C;     // 5760
static constexpr int ST_FLOATS = TILE * TGT_C;      // 5440
static constexpr int SP_BYTES  = SP_FLOATS * 4;     // 23040
static constexpr int ST_BYTES  = ST_FLOATS * 4;     // 21760
static constexpr int TILE_BYTES = SP_BYTES + ST_BYTES;       // 44800
static constexpr int DYN_SMEM  = STAGES * TILE_BYTES + 128;  // 179328

__device__ float    g_partials[NBLOCKS * 4];
__device__ unsigned g_count = 0;

// ---- PTX helpers ----
__device__ __forceinline__ uint32_t smem_u32(const void* p) {
    return (uint32_t)__cvta_generic_to_shared(p);
}
#define MBAR_INIT(addr, cnt) \
    asm volatile("mbarrier.init.shared.b64 [%0], %1;" :: "r"(addr), "r"(cnt) : "memory")
#define MBAR_EXPECT_TX(addr, bytes) \
    asm volatile("mbarrier.arrive.expect_tx.shared.b64 _, [%0], %1;" :: "r"(addr), "r"(bytes) : "memory")
#define MBAR_ARRIVE(addr) \
    asm volatile("mbarrier.arrive.shared.b64 _, [%0];" :: "r"(addr) : "memory")
#define MBAR_WAIT_PARITY(addr, ph) do {                                        \
    asm volatile("{\n\t.reg .pred P1;\n"                                       \
                 "WL_%=:\n\t"                                                  \
                 "mbarrier.try_wait.parity.acquire.cta.shared::cta.b64 P1, [%0], %1;\n\t" \
                 "@!P1 bra WL_%=;\n\t}"                                        \
                 :: "r"(addr), "r"(ph) : "memory");                            \
} while (0)
#define BULK_G2S(dst_smem, src_gmem, bytes, mbar) \
    asm volatile("cp.async.bulk.shared::cluster.global.mbarrier::complete_tx::bytes " \
                 "[%0], [%1], %2, [%3];"                                       \
                 :: "r"(dst_smem), "l"(src_gmem), "r"(bytes), "r"(mbar) : "memory")

__device__ __forceinline__ float iou_cxcywh(float ax, float ay, float aw, float ah,
                                            float bx, float by, float bw, float bh) {
    float ax1 = ax - aw * 0.5f, ay1 = ay - ah * 0.5f;
    float ax2 = ax + aw * 0.5f, ay2 = ay + ah * 0.5f;
    float bx1 = bx - bw * 0.5f, by1 = by - bh * 0.5f;
    float bx2 = bx + bw * 0.5f, by2 = by + bh * 0.5f;
    float iw = fmaxf(fminf(ax2, bx2) - fmaxf(ax1, bx1), 0.0f);
    float ih = fmaxf(fminf(ay2, by2) - fmaxf(ay1, by1), 0.0f);
    float inter  = iw * ih;
    float area_a = (ax2 - ax1) * (ay2 - ay1);
    float area_b = (bx2 - bx1) * (by2 - by1);
    return inter / (area_a + area_b - inter);
}

__device__ __forceinline__ float sgnsqrt(float x) {
    float s = (x > 0.0f) ? 1.0f : ((x < 0.0f) ? -1.0f : 0.0f);
    return s * sqrtf(fabsf(x) + 1e-6f);
}

// Full per-cell box/obj/noobj math (reference semantics).
__device__ __forceinline__ void cell_box_math(
    const float* __restrict__ pb,   // preds[80..89]
    const float* __restrict__ tb,   // target[80..84]
    float& aC, float& aO, float& aN) {
    float p80 = pb[0];
    float b2x = pb[1], b2y = pb[2], b2w = pb[3], b2h = pb[4];
    float p85 = pb[5];
    float b1x = pb[6], b1y = pb[7], b1w = pb[8], b1h = pb[9];
    float obj = tb[0];
    float tbx = tb[1], tby = tb[2], tbw = tb[3], tbh = tb[4];

    float iou1 = iou_cxcywh(b1x, b1y, b1w, b1h, tbx, tby, tbw, tbh);
    float iou2 = iou_cxcywh(b2x, b2y, b2w, b2h, tbx, tby, tbw, tbh);
    bool pick2 = iou2 > iou1;   // numpy argmax: first max wins ties

    float bx = pick2 ? b2x : b1x;
    float bw = pick2 ? b2w : b1w;
    float bh = pick2 ? b2h : b1h;
    float op = pick2 ? p80 : p85;

    // pred_boxes = obj * chosen box; center loss uses cx only ([..., :-3])
    float dc = fmaf(obj, bx, -tbx);
    aC = fmaf(dc, dc, aC);
    float dw = sgnsqrt(obj * bw) - sqrtf(tbw);
    aC = fmaf(dw, dw, aC);
    float dh = sgnsqrt(obj * bh) - sqrtf(tbh);
    aC = fmaf(dh, dh, aC);

    float e1 = fmaf(obj, op, -obj);
    aO = fmaf(e1, e1, aO);
    float e2 = fmaf(1.0f - obj, op, -obj);
    aN = fmaf(e2, e2, aN);
}

__global__ __launch_bounds__(THREADS)
void yolo_loss_tma(const float* __restrict__ P, const float* __restrict__ T,
                   float* __restrict__ out, int ncells) {
    extern __shared__ __align__(16) unsigned char dyn[];
    float* spb[STAGES];  float* stb[STAGES];
    #pragma unroll
    for (int s = 0; s < STAGES; s++) {
        spb[s] = (float*)(dyn + s * TILE_BYTES);
        stb[s] = spb[s] + SP_FLOATS;
    }
    uint64_t* bars = (uint64_t*)(dyn + STAGES * TILE_BYTES);  // [0..3]=full,[4..7]=empty
    uint32_t full_a[STAGES], empty_a[STAGES];
    #pragma unroll
    for (int s = 0; s < STAGES; s++) {
        full_a[s]  = smem_u32(&bars[s]);
        empty_a[s] = smem_u32(&bars[STAGES + s]);
    }

    __shared__ float  red[4][WARPS];
    __shared__ double dred[4][WARPS];
    __shared__ int    s_last;

    const unsigned FULL = 0xffffffffu;
    const int tid  = threadIdx.x;
    const int lane = tid & 31;
    const int wrp  = tid >> 5;

    const int ntiles = ncells / TILE;
    const int rem    = ncells - ntiles * TILE;
    const int nmine = ((int)blockIdx.x < ntiles)
                    ? (ntiles - 1 - (int)blockIdx.x) / (int)gridDim.x + 1 : 0;

    if (tid == 0) {
        #pragma unroll
        for (int s = 0; s < STAGES; s++) {
            MBAR_INIT(full_a[s], 1);
            MBAR_INIT(empty_a[s], WARPS);
        }
    }
    __syncthreads();

    // ---- Prologue: issue up to STAGES tiles ----
    if (tid == 0) {
        int pre = nmine < STAGES ? nmine : STAGES;
        for (int i = 0; i < pre; i++) {
            int tl = blockIdx.x + i * gridDim.x;
            MBAR_EXPECT_TX(full_a[i], TILE_BYTES);
            BULK_G2S(smem_u32(spb[i]), P + (size_t)tl * SP_FLOATS, SP_BYTES, full_a[i]);
            BULK_G2S(smem_u32(stb[i]), T + (size_t)tl * ST_FLOATS, ST_BYTES, full_a[i]);
        }
    }

    float aC = 0.0f, aO = 0.0f, aN = 0.0f, aL = 0.0f;
    const int cc = tid >> 3;          // cell for class loss (8 threads/cell)
    const int k0 = (tid & 7) * 10;    // class sub-range start
    const int bc = tid - (THREADS - TILE);   // box-math cell (warps 14-15)

    for (int it = 0; it < nmine; it++) {
        const int b  = it & (STAGES - 1);
        const int ph = (it / STAGES) & 1;
        MBAR_WAIT_PARITY(full_a[b], ph);

        const float* sp = spb[b];
        const float* st = stb[b];

        // ---- class loss: 8 threads/cell, 10 classes; pred via float2 ----
        {
            // pred float offset = cc*90 + (tid&7)*10 -> even -> 8B aligned
            const float2* pc2 = (const float2*)(sp + cc * PRED_C + k0);
            const float*  tc  = st + cc * TGT_C;
            float obj = tc[80];
            const float* tk = tc + k0;
            float l0 = 0.0f, l1 = 0.0f;
            #pragma unroll
            for (int j = 0; j < 5; j++) {
                float2 pv = pc2[j];
                float d0 = fmaf(pv.x, obj, -tk[2 * j]);     l0 = fmaf(d0, d0, l0);
                float d1 = fmaf(pv.y, obj, -tk[2 * j + 1]); l1 = fmaf(d1, d1, l1);
            }
            aL += l0 + l1;
        }

        // ---- box math: one thread/cell on warps 14-15 (away from producer) ----
        if (bc >= 0) {
            cell_box_math(sp + bc * PRED_C + 80, st + bc * TGT_C + 80, aC, aO, aN);
        }

        // ---- per-warp empty arrive ----
        __syncwarp();
        if (lane == 0) MBAR_ARRIVE(empty_a[b]);

        // ---- producer: refill this stage for tile it+STAGES ----
        if (tid == 0) {
            int ti = it + STAGES;
            if (ti < nmine) {
                MBAR_WAIT_PARITY(empty_a[b], ph);
                int tl = blockIdx.x + ti * gridDim.x;
                MBAR_EXPECT_TX(full_a[b], TILE_BYTES);
                BULK_G2S(smem_u32(spb[b]), P + (size_t)tl * SP_FLOATS, SP_BYTES, full_a[b]);
                BULK_G2S(smem_u32(stb[b]), T + (size_t)tl * ST_FLOATS, ST_BYTES, full_a[b]);
            }
        }
    }

    // ---- remainder cells (not taken for 401408): block 0, direct global ----
    if (rem > 0 && blockIdx.x == 0 && tid < rem) {
        int cell = ntiles * TILE + tid;
        const float* p = P + (size_t)cell * PRED_C;
        const float* t = T + (size_t)cell * TGT_C;
        float obj = t[80];
        for (int k = 0; k < 80; k++) {
            float d = fmaf(p[k], obj, -t[k]);
            aL = fmaf(d, d, aL);
        }
        float pb[10], tb[5];
        #pragma unroll
        for (int k = 0; k < 10; k++) pb[k] = p[80 + k];
        #pragma unroll
        for (int k = 0; k < 5; k++)  tb[k] = t[80 + k];
        cell_box_math(pb, tb, aC, aO, aN);
    }

    // ---- Block reduction ----
    #pragma unroll
    for (int off = 16; off > 0; off >>= 1) {
        aC += __shfl_xor_sync(FULL, aC, off);
        aO += __shfl_xor_sync(FULL, aO, off);
        aN += __shfl_xor_sync(FULL, aN, off);
        aL += __shfl_xor_sync(FULL, aL, off);
    }
    if (lane == 0) {
        red[0][wrp] = aC; red[1][wrp] = aO; red[2][wrp] = aN; red[3][wrp] = aL;
    }
    __syncthreads();
    if (tid == 0) {
        float s0 = 0, s1 = 0, s2 = 0, s3 = 0;
        #pragma unroll
        for (int w = 0; w < WARPS; w++) {
            s0 += red[0][w]; s1 += red[1][w]; s2 += red[2][w]; s3 += red[3][w];
        }
        g_partials[blockIdx.x * 4 + 0] = s0;
        g_partials[blockIdx.x * 4 + 1] = s1;
        g_partials[blockIdx.x * 4 + 2] = s2;
        g_partials[blockIdx.x * 4 + 3] = s3;
        __threadfence();
        unsigned prev = atomicAdd(&g_count, 1u);
        s_last = (prev == gridDim.x - 1) ? 1 : 0;
    }
    __syncthreads();

    // ---- Last block finalizes & resets counter for graph replay ----
    if (s_last) {
        double v0 = 0, v1 = 0, v2 = 0, v3 = 0;
        for (int b = tid; b < (int)gridDim.x; b += THREADS) {
            v0 += (double)__ldcg(&g_partials[b * 4 + 0]);
            v1 += (double)__ldcg(&g_partials[b * 4 + 1]);
            v2 += (double)__ldcg(&g_partials[b * 4 + 2]);
            v3 += (double)__ldcg(&g_partials[b * 4 + 3]);
        }
        #pragma unroll
        for (int off = 16; off > 0; off >>= 1) {
            v0 += __shfl_xor_sync(FULL, v0, off);
            v1 += __shfl_xor_sync(FULL, v1, off);
            v2 += __shfl_xor_sync(FULL, v2, off);
            v3 += __shfl_xor_sync(FULL, v3, off);
        }
        if (lane == 0) {
            dred[0][wrp] = v0; dred[1][wrp] = v1; dred[2][wrp] = v2; dred[3][wrp] = v3;
        }
        __syncthreads();
        if (tid == 0) {
            double c = 0, o = 0, n = 0, cl = 0;
            #pragma unroll
            for (int w = 0; w < WARPS; w++) {
                c += dred[0][w]; o += dred[1][w]; n += dred[2][w]; cl += dred[3][w];
            }
            out[0] = (float)(c * 5.0);   // coords (LAMBDA_COORDS)
            out[1] = (float)o;           // obj
            out[2] = (float)(n * 0.5);   // noobj (LAMBDA_NOOBJ)
            out[3] = (float)cl;          // classes
            atomicExch(&g_count, 0u);    // reset for next graph replay
        }
    }
}

extern "C" void kernel_launch(void* const* d_in, const int* in_sizes, int n_in,
                              void* d_out, int out_size) {
    const float* P = (const float*)d_in[0];   // predictions
    const float* T = (const float*)d_in[1];   // target
    float* out = (float*)d_out;

    int ncells = in_sizes[0] / PRED_C;        // 8192*7*7 = 401408

    cudaFuncSetAttribute(yolo_loss_tma,
                         cudaFuncAttributeMaxDynamicSharedMemorySize, DYN_SMEM);
    yolo_loss_tma<<<NBLOCKS, THREADS, DYN_SMEM>>>(P, T, out, ncells);
}

// round 10
// speedup vs baseline: 1.4358x; 1.4306x over previous
#include <cuda_runtime.h>
#include <math.h>
#include <stdint.h>

// ---------------------------------------------------------------------------
// YoloLoss: predictions (N,7,7,90) f32, target (N,7,7,85) f32 -> 4 scalars
// Warp-specialized cp.async.bulk pipeline: 2 stages x 64-cell tiles,
// 304 blocks (2/SM), 288 threads (warp 0 = producer, warps 1-8 = consumers).
//   - producer loops independently: empty-wait -> expect_tx -> 2 bulk copies
//   - consumers: 4 threads/cell class loss (float2 LDS), 1 thread/cell box math
//   - per-warp empty arrives (count = 8)
//   - last-block-done fused finalize (self-resets for graph replay)
// ---------------------------------------------------------------------------

#define PRED_C 90
#define TGT_C  85

static constexpr int THREADS   = 288;               // 9 warps
static constexpr int WARPS     = THREADS / 32;
static constexpr int CWARPS    = 8;                 // consumer warps
static constexpr int NBLOCKS   = 304;               // 2 per SM
static constexpr int STAGES    = 2;
static constexpr int TILE      = 64;                // cells per tile
static constexpr int SP_FLOATS = TILE * PRED_C;     // 5760
static constexpr int ST_FLOATS = TILE * TGT_C;      // 5440
static constexpr int SP_BYTES  = SP_FLOATS * 4;     // 23040
static constexpr int ST_BYTES  = ST_FLOATS * 4;     // 21760
static constexpr int TILE_BYTES = SP_BYTES + ST_BYTES;       // 44800
static constexpr int DYN_SMEM  = STAGES * TILE_BYTES + 128;  // 89728

__device__ float    g_partials[NBLOCKS * 4];
__device__ unsigned g_count = 0;

// ---- PTX helpers ----
__device__ __forceinline__ uint32_t smem_u32(const void* p) {
    return (uint32_t)__cvta_generic_to_shared(p);
}
#define MBAR_INIT(addr, cnt) \
    asm volatile("mbarrier.init.shared.b64 [%0], %1;" :: "r"(addr), "r"(cnt) : "memory")
#define MBAR_EXPECT_TX(addr, bytes) \
    asm volatile("mbarrier.arrive.expect_tx.shared.b64 _, [%0], %1;" :: "r"(addr), "r"(bytes) : "memory")
#define MBAR_ARRIVE(addr) \
    asm volatile("mbarrier.arrive.shared.b64 _, [%0];" :: "r"(addr) : "memory")
#define MBAR_WAIT_PARITY(addr, ph) do {                                        \
    asm volatile("{\n\t.reg .pred P1;\n"                                       \
                 "WL_%=:\n\t"                                                  \
                 "mbarrier.try_wait.parity.acquire.cta.shared::cta.b64 P1, [%0], %1;\n\t" \
                 "@!P1 bra WL_%=;\n\t}"                                        \
                 :: "r"(addr), "r"(ph) : "memory");                            \
} while (0)
#define BULK_G2S(dst_smem, src_gmem, bytes, mbar) \
    asm volatile("cp.async.bulk.shared::cluster.global.mbarrier::complete_tx::bytes " \
                 "[%0], [%1], %2, [%3];"                                       \
                 :: "r"(dst_smem), "l"(src_gmem), "r"(bytes), "r"(mbar) : "memory")

__device__ __forceinline__ float iou_cxcywh(float ax, float ay, float aw, float ah,
                                            float bx, float by, float bw, float bh) {
    float ax1 = ax - aw * 0.5f, ay1 = ay - ah * 0.5f;
    float ax2 = ax + aw * 0.5f, ay2 = ay + ah * 0.5f;
    float bx1 = bx - bw * 0.5f, by1 = by - bh * 0.5f;
    float bx2 = bx + bw * 0.5f, by2 = by + bh * 0.5f;
    float iw = fmaxf(fminf(ax2, bx2) - fmaxf(ax1, bx1), 0.0f);
    float ih = fmaxf(fminf(ay2, by2) - fmaxf(ay1, by1), 0.0f);
    float inter  = iw * ih;
    float area_a = (ax2 - ax1) * (ay2 - ay1);
    float area_b = (bx2 - bx1) * (by2 - by1);
    return inter / (area_a + area_b - inter);
}

__device__ __forceinline__ float sgnsqrt(float x) {
    float s = (x > 0.0f) ? 1.0f : ((x < 0.0f) ? -1.0f : 0.0f);
    return s * sqrtf(fabsf(x) + 1e-6f);
}

// Full per-cell box/obj/noobj math (reference semantics).
__device__ __forceinline__ void cell_box_math(
    const float* __restrict__ pb,   // preds[80..89]
    const float* __restrict__ tb,   // target[80..84]
    float& aC, float& aO, float& aN) {
    float p80 = pb[0];
    float b2x = pb[1], b2y = pb[2], b2w = pb[3], b2h = pb[4];
    float p85 = pb[5];
    float b1x = pb[6], b1y = pb[7], b1w = pb[8], b1h = pb[9];
    float obj = tb[0];
    float tbx = tb[1], tby = tb[2], tbw = tb[3], tbh = tb[4];

    float iou1 = iou_cxcywh(b1x, b1y, b1w, b1h, tbx, tby, tbw, tbh);
    float iou2 = iou_cxcywh(b2x, b2y, b2w, b2h, tbx, tby, tbw, tbh);
    bool pick2 = iou2 > iou1;   // numpy argmax: first max wins ties

    float bx = pick2 ? b2x : b1x;
    float bw = pick2 ? b2w : b1w;
    float bh = pick2 ? b2h : b1h;
    float op = pick2 ? p80 : p85;

    // pred_boxes = obj * chosen box; center loss uses cx only ([..., :-3])
    float dc = fmaf(obj, bx, -tbx);
    aC = fmaf(dc, dc, aC);
    float dw = sgnsqrt(obj * bw) - sqrtf(tbw);
    aC = fmaf(dw, dw, aC);
    float dh = sgnsqrt(obj * bh) - sqrtf(tbh);
    aC = fmaf(dh, dh, aC);

    float e1 = fmaf(obj, op, -obj);
    aO = fmaf(e1, e1, aO);
    float e2 = fmaf(1.0f - obj, op, -obj);
    aN = fmaf(e2, e2, aN);
}

__global__ __launch_bounds__(THREADS)
void yolo_loss_ws(const float* __restrict__ P, const float* __restrict__ T,
                  float* __restrict__ out, int ncells) {
    extern __shared__ __align__(16) unsigned char dyn[];
    float* spb[STAGES];  float* stb[STAGES];
    #pragma unroll
    for (int s = 0; s < STAGES; s++) {
        spb[s] = (float*)(dyn + s * TILE_BYTES);
        stb[s] = spb[s] + SP_FLOATS;
    }
    uint64_t* bars = (uint64_t*)(dyn + STAGES * TILE_BYTES);  // [0..1]=full,[2..3]=empty
    uint32_t full_a[STAGES], empty_a[STAGES];
    #pragma unroll
    for (int s = 0; s < STAGES; s++) {
        full_a[s]  = smem_u32(&bars[s]);
        empty_a[s] = smem_u32(&bars[STAGES + s]);
    }

    __shared__ float  red[4][WARPS];
    __shared__ double dred[4][WARPS];
    __shared__ int    s_last;

    const unsigned FULL = 0xffffffffu;
    const int tid  = threadIdx.x;
    const int lane = tid & 31;
    const int wrp  = tid >> 5;

    const int ntiles = ncells / TILE;
    const int rem    = ncells - ntiles * TILE;
    const int nmine = ((int)blockIdx.x < ntiles)
                    ? (ntiles - 1 - (int)blockIdx.x) / (int)gridDim.x + 1 : 0;

    if (tid == 0) {
        #pragma unroll
        for (int s = 0; s < STAGES; s++) {
            MBAR_INIT(full_a[s], 1);
            MBAR_INIT(empty_a[s], CWARPS);
        }
    }
    __syncthreads();

    float aC = 0.0f, aO = 0.0f, aN = 0.0f, aL = 0.0f;

    if (wrp == 0) {
        // ================= PRODUCER (warp 0, lane 0 issues) =================
        if (lane == 0) {
            for (int it = 0; it < nmine; it++) {
                const int b = it & (STAGES - 1);
                const int r = it >> 1;            // round for this buffer
                if (r >= 1) {
                    MBAR_WAIT_PARITY(empty_a[b], (r - 1) & 1);
                }
                int tl = blockIdx.x + it * gridDim.x;
                MBAR_EXPECT_TX(full_a[b], TILE_BYTES);
                BULK_G2S(smem_u32(spb[b]), P + (size_t)tl * SP_FLOATS, SP_BYTES, full_a[b]);
                BULK_G2S(smem_u32(stb[b]), T + (size_t)tl * ST_FLOATS, ST_BYTES, full_a[b]);
            }
        }
    } else {
        // ================= CONSUMERS (warps 1-8, 256 threads) ===============
        const int ctid = tid - 32;
        const int cc = ctid >> 2;          // cell (4 threads/cell)
        const int k0 = (ctid & 3) * 20;    // class sub-range (even -> 8B aligned)

        for (int it = 0; it < nmine; it++) {
            const int b  = it & (STAGES - 1);
            const int ph = (it >> 1) & 1;
            MBAR_WAIT_PARITY(full_a[b], ph);

            const float* sp = spb[b];
            const float* st = stb[b];

            // ---- class loss: 4 threads/cell, 20 classes via float2 ----
            {
                const float2* pc2 = (const float2*)(sp + cc * PRED_C + k0);
                const float*  tc  = st + cc * TGT_C;
                float obj = tc[80];
                const float* tk = tc + k0;
                float l0 = 0.0f, l1 = 0.0f;
                #pragma unroll
                for (int j = 0; j < 10; j++) {
                    float2 pv = pc2[j];
                    float d0 = fmaf(pv.x, obj, -tk[2 * j]);     l0 = fmaf(d0, d0, l0);
                    float d1 = fmaf(pv.y, obj, -tk[2 * j + 1]); l1 = fmaf(d1, d1, l1);
                }
                aL += l0 + l1;
            }

            // ---- box math: one thread per cell (consumer tids 0..63) ----
            if (ctid < TILE) {
                cell_box_math(sp + ctid * PRED_C + 80, st + ctid * TGT_C + 80,
                              aC, aO, aN);
            }

            // ---- per-warp empty arrive ----
            __syncwarp();
            if (lane == 0) MBAR_ARRIVE(empty_a[b]);
        }
    }

    // ---- remainder cells (not taken for 401408): block 0, direct global ----
    if (rem > 0 && blockIdx.x == 0 && tid < rem) {
        int cell = ntiles * TILE + tid;
        const float* p = P + (size_t)cell * PRED_C;
        const float* t = T + (size_t)cell * TGT_C;
        float obj = t[80];
        for (int k = 0; k < 80; k++) {
            float d = fmaf(p[k], obj, -t[k]);
            aL = fmaf(d, d, aL);
        }
        float pb[10], tb[5];
        #pragma unroll
        for (int k = 0; k < 10; k++) pb[k] = p[80 + k];
        #pragma unroll
        for (int k = 0; k < 5; k++)  tb[k] = t[80 + k];
        cell_box_math(pb, tb, aC, aO, aN);
    }

    // ---- Block reduction ----
    #pragma unroll
    for (int off = 16; off > 0; off >>= 1) {
        aC += __shfl_xor_sync(FULL, aC, off);
        aO += __shfl_xor_sync(FULL, aO, off);
        aN += __shfl_xor_sync(FULL, aN, off);
        aL += __shfl_xor_sync(FULL, aL, off);
    }
    if (lane == 0) {
        red[0][wrp] = aC; red[1][wrp] = aO; red[2][wrp] = aN; red[3][wrp] = aL;
    }
    __syncthreads();
    if (tid == 0) {
        float s0 = 0, s1 = 0, s2 = 0, s3 = 0;
        #pragma unroll
        for (int w = 0; w < WARPS; w++) {
            s0 += red[0][w]; s1 += red[1][w]; s2 += red[2][w]; s3 += red[3][w];
        }
        g_partials[blockIdx.x * 4 + 0] = s0;
        g_partials[blockIdx.x * 4 + 1] = s1;
        g_partials[blockIdx.x * 4 + 2] = s2;
        g_partials[blockIdx.x * 4 + 3] = s3;
        __threadfence();
        unsigned prev = atomicAdd(&g_count, 1u);
        s_last = (prev == gridDim.x - 1) ? 1 : 0;
    }
    __syncthreads();

    // ---- Last block finalizes & resets counter for graph replay ----
    if (s_last) {
        double v0 = 0, v1 = 0, v2 = 0, v3 = 0;
        for (int b = tid; b < (int)gridDim.x; b += THREADS) {
            v0 += (double)__ldcg(&g_partials[b * 4 + 0]);
            v1 += (double)__ldcg(&g_partials[b * 4 + 1]);
            v2 += (double)__ldcg(&g_partials[b * 4 + 2]);
            v3 += (double)__ldcg(&g_partials[b * 4 + 3]);
        }
        #pragma unroll
        for (int off = 16; off > 0; off >>= 1) {
            v0 += __shfl_xor_sync(FULL, v0, off);
            v1 += __shfl_xor_sync(FULL, v1, off);
            v2 += __shfl_xor_sync(FULL, v2, off);
            v3 += __shfl_xor_sync(FULL, v3, off);
        }
        if (lane == 0) {
            dred[0][wrp] = v0; dred[1][wrp] = v1; dred[2][wrp] = v2; dred[3][wrp] = v3;
        }
        __syncthreads();
        if (tid == 0) {
            double c = 0, o = 0, n = 0, cl = 0;
            #pragma unroll
            for (int w = 0; w < WARPS; w++) {
                c += dred[0][w]; o += dred[1][w]; n += dred[2][w]; cl += dred[3][w];
            }
            out[0] = (float)(c * 5.0);   // coords (LAMBDA_COORDS)
            out[1] = (float)o;           // obj
            out[2] = (float)(n * 0.5);   // noobj (LAMBDA_NOOBJ)
            out[3] = (float)cl;          // classes
            atomicExch(&g_count, 0u);    // reset for next graph replay
        }
    }
}

extern "C" void kernel_launch(void* const* d_in, const int* in_sizes, int n_in,
                              void* d_out, int out_size) {
    const float* P = (const float*)d_in[0];   // predictions
    const float* T = (const float*)d_in[1];   // target
    float* out = (float*)d_out;

    int ncells = in_sizes[0] / PRED_C;        // 8192*7*7 = 401408

    cudaFuncSetAttribute(yolo_loss_ws,
                         cudaFuncAttributeMaxDynamicSharedMemorySize, DYN_SMEM);
    yolo_loss_ws<<<NBLOCKS, THREADS, DYN_SMEM>>>(P, T, out, ncells);
}